// round 1
// baseline (speedup 1.0000x reference)
#include <cuda_runtime.h>
#include <cstdint>

#define T_STEPS 512
#define BATCH   64
#define IN_DIM  256
#define HID     512
#define OUT_DIM 256
#define G4      2048   // 4*HID

#define NCTA     128
#define RTHREADS 256

#define SW_STRIDE 520              // 512 + 8 pad
#define SH_STRIDE 68               // 64 + 4 pad
#define SW_FLOATS (16 * SW_STRIDE) // 8320
#define SH_CHUNK  (64 * SH_STRIDE) // 4352 floats per (half,buf) chunk
#define SH_BASE   SW_FLOATS
#define SRED_BASE (SH_BASE + 4 * SH_CHUNK)   // 25728
#define SMEM_FLOATS (SRED_BASE + 128 * 8)    // 26752
#define SMEM_BYTES  (SMEM_FLOATS * 4)        // 107008

#define OFF_H ((size_t)T_STEPS * BATCH * OUT_DIM)       // 8388608
#define OFF_C (OFF_H + (size_t)BATCH * HID)             // 8421376

// ---------------- persistent device state ----------------
__device__ float    g_xg[(size_t)T_STEPS * BATCH * G4];   // x-gate precompute (256MB)
__device__ float    g_hs[(size_t)T_STEPS * BATCH * HID];  // h history (64MB)
__device__ float    g_bsum[G4];
__device__ unsigned g_bar;

// ---------------- reset (per replay) ----------------
__global__ void reset_kernel(const float* __restrict__ b_ih,
                             const float* __restrict__ b_hh) {
    int idx = blockIdx.x * blockDim.x + threadIdx.x;
    if (idx == 0) g_bar = 0u;
    if (idx < G4) g_bsum[idx] = b_ih[idx] + b_hh[idx];
}

// ---------------- generic C[m][n] = sum_k A[m][k]*B[n][k] + bias[n] ----------
// 64x64 tile, BK=16, 256 threads, 4x4 microtile.
__global__ __launch_bounds__(256) void gemm_tn64(
    const float* __restrict__ A, const float* __restrict__ Bm,
    const float* __restrict__ bias, float* __restrict__ C,
    int M, int N, int K)
{
    __shared__ float As[16][64];
    __shared__ float Bs[16][64];
    const int tid = threadIdx.x;
    const int m0 = blockIdx.y * 64, n0 = blockIdx.x * 64;
    const int r  = tid >> 2;
    const int kq = (tid & 3) << 2;
    const int tx = tid & 15, ty = tid >> 4;

    float acc[4][4] = {};

    for (int k0 = 0; k0 < K; k0 += 16) {
        float4 av = *(const float4*)(A  + (size_t)(m0 + r) * K + k0 + kq);
        float4 bv = *(const float4*)(Bm + (size_t)(n0 + r) * K + k0 + kq);
        As[kq + 0][r] = av.x; As[kq + 1][r] = av.y;
        As[kq + 2][r] = av.z; As[kq + 3][r] = av.w;
        Bs[kq + 0][r] = bv.x; Bs[kq + 1][r] = bv.y;
        Bs[kq + 2][r] = bv.z; Bs[kq + 3][r] = bv.w;
        __syncthreads();
        #pragma unroll
        for (int kk = 0; kk < 16; kk++) {
            float4 a4 = *(const float4*)&As[kk][ty << 2];
            float4 b4 = *(const float4*)&Bs[kk][tx << 2];
            float a[4] = {a4.x, a4.y, a4.z, a4.w};
            float b[4] = {b4.x, b4.y, b4.z, b4.w};
            #pragma unroll
            for (int i2 = 0; i2 < 4; i2++)
                #pragma unroll
                for (int j2 = 0; j2 < 4; j2++)
                    acc[i2][j2] = fmaf(a[i2], b[j2], acc[i2][j2]);
        }
        __syncthreads();
    }

    const int ncol = n0 + (tx << 2);
    float4 bb = *(const float4*)(bias + ncol);
    #pragma unroll
    for (int i2 = 0; i2 < 4; i2++) {
        int mrow = m0 + (ty << 2) + i2;
        float4 o;
        o.x = acc[i2][0] + bb.x;
        o.y = acc[i2][1] + bb.y;
        o.z = acc[i2][2] + bb.z;
        o.w = acc[i2][3] + bb.w;
        *(float4*)(C + (size_t)mrow * N + ncol) = o;
    }
}

// ---------------- persistent recurrent kernel ----------------
__device__ __forceinline__ float sigf(float x) { return 1.f / (1.f + __expf(-x)); }

__device__ __forceinline__ void cp_async16(float* dst_smem, const float* src) {
    unsigned d = (unsigned)__cvta_generic_to_shared(dst_smem);
    asm volatile("cp.async.cg.shared.global [%0], [%1], 16;" :: "r"(d), "l"(src) : "memory");
}

__global__ void __launch_bounds__(RTHREADS, 1)
lstm_recurrent(const float* __restrict__ W_hh, float* __restrict__ out)
{
    extern __shared__ float smem[];
    const int tid = threadIdx.x;
    const int j0  = blockIdx.x << 2;    // this CTA owns h columns [j0, j0+4)
    const int hk  = tid >> 7;           // K-half: 0 -> k in [0,256), 1 -> [256,512)
    const int t2  = tid & 127;
    const int bq  = t2 & 31;            // handles batch rows bq and bq+32
    const int ii  = t2 >> 5;            // which of the 4 owned h columns
    const int j   = j0 + ii;

    // --- load W_hh slice into smem: rows {q*512 + j0 + i}, r = q*4 + i ---
    #pragma unroll
    for (int u = 0; u < 8; u++) {
        int f4 = u * 256 + tid;          // 0..2047 float4s
        int rr = f4 >> 7;                // 0..15
        int kk = (f4 & 127) << 2;        // 0..508
        int q  = rr >> 2, iw = rr & 3;
        float4 v = *(const float4*)(W_hh + (size_t)(q * HID + j0 + iw) * HID + kk);
        *(float4*)(smem + rr * SW_STRIDE + kk) = v;
    }
    __syncthreads();

    float c0 = 0.f, c1 = 0.f;

    for (int t = 0; t < T_STEPS; t++) {
        float acc[2][4] = {{0.f, 0.f, 0.f, 0.f}, {0.f, 0.f, 0.f, 0.f}};

        // x-gate contributions for this thread's outputs (only hk==0 needs them)
        float xg[2][4];
        if (hk == 0) {
            const float* xp = g_xg + (size_t)t * BATCH * G4;
            #pragma unroll
            for (int q = 0; q < 4; q++) {
                xg[0][q] = xp[(size_t)bq * G4        + q * HID + j];
                xg[1][q] = xp[(size_t)(bq + 32) * G4 + q * HID + j];
            }
        }

        if (t > 0) {
            const float* hsrc = g_hs + (size_t)(t - 1) * (BATCH * HID);

            // prefetch chunk 0 into buf 0 (each K-half loads its own chunks)
            {
                float* dst = smem + SH_BASE + (hk * 2 + 0) * SH_CHUNK;
                const int kbase = hk * 256;
                #pragma unroll
                for (int u = 0; u < 8; u++) {
                    int f4 = u * 128 + t2;
                    int b  = f4 >> 4;
                    int kq = (f4 & 15) << 2;
                    cp_async16(dst + b * SH_STRIDE + kq,
                               hsrc + (size_t)b * HID + kbase + kq);
                }
                asm volatile("cp.async.commit_group;" ::: "memory");
            }

            #pragma unroll
            for (int ci = 0; ci < 4; ci++) {
                if (ci < 3) {
                    const int buf = (ci + 1) & 1;
                    float* dst = smem + SH_BASE + (hk * 2 + buf) * SH_CHUNK;
                    const int kbase = hk * 256 + (ci + 1) * 64;
                    #pragma unroll
                    for (int u = 0; u < 8; u++) {
                        int f4 = u * 128 + t2;
                        int b  = f4 >> 4;
                        int kq = (f4 & 15) << 2;
                        cp_async16(dst + b * SH_STRIDE + kq,
                                   hsrc + (size_t)b * HID + kbase + kq);
                    }
                    asm volatile("cp.async.commit_group;" ::: "memory");
                    asm volatile("cp.async.wait_group 1;" ::: "memory");
                } else {
                    asm volatile("cp.async.wait_group 0;" ::: "memory");
                }
                __syncthreads();

                const float* shp = smem + SH_BASE + (hk * 2 + (ci & 1)) * SH_CHUNK;
                const int kw = hk * 256 + ci * 64;   // k offset into sW rows
                #pragma unroll
                for (int kk = 0; kk < 64; kk += 4) {
                    float4 h0 = *(const float4*)(shp + bq * SH_STRIDE + kk);
                    float4 h1 = *(const float4*)(shp + (bq + 32) * SH_STRIDE + kk);
                    #pragma unroll
                    for (int q = 0; q < 4; q++) {
                        float4 w = *(const float4*)(smem + (q * 4 + ii) * SW_STRIDE + kw + kk);
                        acc[0][q] = fmaf(h0.x, w.x, acc[0][q]);
                        acc[0][q] = fmaf(h0.y, w.y, acc[0][q]);
                        acc[0][q] = fmaf(h0.z, w.z, acc[0][q]);
                        acc[0][q] = fmaf(h0.w, w.w, acc[0][q]);
                        acc[1][q] = fmaf(h1.x, w.x, acc[1][q]);
                        acc[1][q] = fmaf(h1.y, w.y, acc[1][q]);
                        acc[1][q] = fmaf(h1.z, w.z, acc[1][q]);
                        acc[1][q] = fmaf(h1.w, w.w, acc[1][q]);
                    }
                }
                __syncthreads();
            }
        }

        // --- combine K-halves: hk1 publishes partials, hk0 finishes cell ---
        if (hk == 1) {
            float* rp = smem + SRED_BASE + t2 * 8;
            #pragma unroll
            for (int bb = 0; bb < 2; bb++)
                #pragma unroll
                for (int q = 0; q < 4; q++)
                    rp[bb * 4 + q] = acc[bb][q];
        }
        __syncthreads();

        if (hk == 0) {
            const float* rp = smem + SRED_BASE + t2 * 8;
            #pragma unroll
            for (int bb = 0; bb < 2; bb++)
                #pragma unroll
                for (int q = 0; q < 4; q++)
                    acc[bb][q] += rp[bb * 4 + q];

            // gates (PyTorch order i, f, g, o)
            float i0 = sigf (acc[0][0] + xg[0][0]);
            float f0 = sigf (acc[0][1] + xg[0][1]);
            float gg0 = tanhf(acc[0][2] + xg[0][2]);
            float o0 = sigf (acc[0][3] + xg[0][3]);
            c0 = f0 * c0 + i0 * gg0;
            float h0n = o0 * tanhf(c0);

            float i1 = sigf (acc[1][0] + xg[1][0]);
            float f1 = sigf (acc[1][1] + xg[1][1]);
            float gg1 = tanhf(acc[1][2] + xg[1][2]);
            float o1 = sigf (acc[1][3] + xg[1][3]);
            c1 = f1 * c1 + i1 * gg1;
            float h1n = o1 * tanhf(c1);

            float* hdst = g_hs + (size_t)t * (BATCH * HID);
            hdst[(size_t)bq * HID + j]        = h0n;
            hdst[(size_t)(bq + 32) * HID + j] = h1n;

            if (t == T_STEPS - 1) {
                out[OFF_H + (size_t)bq * HID + j]        = h0n;
                out[OFF_H + (size_t)(bq + 32) * HID + j] = h1n;
                out[OFF_C + (size_t)bq * HID + j]        = c0;
                out[OFF_C + (size_t)(bq + 32) * HID + j] = c1;
            }
        }
        __syncthreads();

        // --- grid-wide barrier (all 128 CTAs co-resident) ---
        if (tid == 0) {
            __threadfence();
            atomicAdd(&g_bar, 1u);
            const unsigned target = (unsigned)(t + 1) * NCTA;
            while (*(volatile unsigned*)&g_bar < target) { }
            __threadfence();
        }
        __syncthreads();
    }
}

// ---------------- launch ----------------
extern "C" void kernel_launch(void* const* d_in, const int* in_sizes, int n_in,
                              void* d_out, int out_size) {
    const float* inputs = (const float*)d_in[0];
    const float* W_ih   = (const float*)d_in[1];
    const float* W_hh   = (const float*)d_in[2];
    const float* b_ih   = (const float*)d_in[3];
    const float* b_hh   = (const float*)d_in[4];
    const float* W_out  = (const float*)d_in[5];
    const float* b_out  = (const float*)d_in[6];
    float* out = (float*)d_out;

    void *xg_p = nullptr, *hs_p = nullptr, *bs_p = nullptr;
    cudaGetSymbolAddress(&xg_p, g_xg);
    cudaGetSymbolAddress(&hs_p, g_hs);
    cudaGetSymbolAddress(&bs_p, g_bsum);

    reset_kernel<<<16, 256>>>(b_ih, b_hh);

    // x_gates = inputs @ W_ih^T + (b_ih + b_hh) : [32768, 2048]
    {
        dim3 grid(G4 / 64, (T_STEPS * BATCH) / 64);
        gemm_tn64<<<grid, 256>>>(inputs, W_ih, (const float*)bs_p, (float*)xg_p,
                                 T_STEPS * BATCH, G4, IN_DIM);
    }

    cudaFuncSetAttribute(lstm_recurrent,
                         cudaFuncAttributeMaxDynamicSharedMemorySize, SMEM_BYTES);
    lstm_recurrent<<<NCTA, RTHREADS, SMEM_BYTES>>>(W_hh, out);

    // outputs = hs @ W_out^T + b_out : [32768, 256]
    {
        dim3 grid(OUT_DIM / 64, (T_STEPS * BATCH) / 64);
        gemm_tn64<<<grid, 256>>>((const float*)hs_p, W_out, b_out, out,
                                 T_STEPS * BATCH, OUT_DIM, HID);
    }
}